// round 4
// baseline (speedup 1.0000x reference)
#include <cuda_runtime.h>

// out[b,s,d] = x[b,s,d] + enc(s,d)
//   enc(s,d) = sin(s / 10000^(d/D)) if d even else cos(s / 10000^(d/D))
// Shapes: B=8, S=4096, D=1024, fp32. 268 MB traffic, pinned at mixed-R/W
// HBM ceiling (~5.9 TB/s across R1-R3 regardless of occ/MLP/cache policy).
//
// R4: Blackwell 256-bit global accesses (ld/st.global.v8.f32, sm_100+).
// 1024B per warp per LDG -> half the LSU ops, half the L1tex wavefronts,
// longer same-direction DRAM bursts. 2 phases x 4 batches keeps live regs
// bounded (~32 data floats/phase).

#define B_ 8
#define S_ 4096
#define D_ 1024
#define SD8_ ((S_ * D_) / 8)   // 524,288 float8 tiles per batch slice

__device__ __forceinline__ void ldg256_cs(const float* p, float* r) {
    asm volatile("ld.global.cs.v8.f32 {%0,%1,%2,%3,%4,%5,%6,%7}, [%8];"
                 : "=f"(r[0]), "=f"(r[1]), "=f"(r[2]), "=f"(r[3]),
                   "=f"(r[4]), "=f"(r[5]), "=f"(r[6]), "=f"(r[7])
                 : "l"(p));
}

__device__ __forceinline__ void stg256_cs(float* p, const float* r) {
    asm volatile("st.global.cs.v8.f32 [%0], {%1,%2,%3,%4,%5,%6,%7,%8};"
                 :: "l"(p),
                    "f"(r[0]), "f"(r[1]), "f"(r[2]), "f"(r[3]),
                    "f"(r[4]), "f"(r[5]), "f"(r[6]), "f"(r[7])
                 : "memory");
}

__global__ __launch_bounds__(256) void pe_add_kernel(
    const float* __restrict__ x, float* __restrict__ out)
{
    const int idx8 = blockIdx.x * blockDim.x + threadIdx.x;   // [0, SD8_)
    const int d0   = (idx8 & (D_ / 8 - 1)) << 3;              // element column in D
    const float sf = (float)(idx8 >> 7);                      // s = idx8 / 128
    const long long off = (long long)idx8 << 3;               // element offset in a slice

    // Encoding for the 8 owned columns. angle(d) = s * exp2(-d*log2(1e4)/D)
    const float c = -(13.287712379549449f / 1024.0f);
    float e[8];
#pragma unroll
    for (int j = 0; j < 8; j += 2) {
        e[j]     = sinf(sf * exp2f((float)(d0 + j)     * c));  // even d
        e[j + 1] = cosf(sf * exp2f((float)(d0 + j + 1) * c));  // odd d
    }

    // 2 phases x 4 batch slices; loads front-batched within a phase.
#pragma unroll
    for (int h = 0; h < 2; h++) {
        float v[4][8];
#pragma unroll
        for (int b = 0; b < 4; b++)
            ldg256_cs(x + (long long)(h * 4 + b) * (S_ * D_) + off, v[b]);
#pragma unroll
        for (int b = 0; b < 4; b++) {
#pragma unroll
            for (int j = 0; j < 8; j++)
                v[b][j] += e[j];
            stg256_cs(out + (long long)(h * 4 + b) * (S_ * D_) + off, v[b]);
        }
    }
}

extern "C" void kernel_launch(void* const* d_in, const int* in_sizes, int n_in,
                              void* d_out, int out_size)
{
    const float* x = (const float*)d_in[0];
    float* out = (float*)d_out;
    pe_add_kernel<<<SD8_ / 256, 256>>>(x, out);
}

// round 5
// speedup vs baseline: 1.0478x; 1.0478x over previous
#include <cuda_runtime.h>

// out[b,s,d] = x[b,s,d] + enc(s,d)
//   enc(s,d) = sin(s / 10000^(d/D)) if d even else cos(s / 10000^(d/D))
// Shapes: B=8, S=4096, D=1024, fp32. 268 MB traffic (algorithmic floor).
//
// FINAL (R5): R1-R4 established the kernel is pinned at the mixed 1:1 R/W
// HBM ceiling (~5.8-6.0 TB/s = ~74% of spec) regardless of occupancy
// (40% vs 82%), MLP (4 vs 8), access width (128b vs 256b), or cache policy.
// This variant = best-measured structure (float4, MLP=8, enc computed once
// per (s,d4) and reused across all 8 batch slices) with default loads +
// evict-first stores (write stream doesn't dirty L2 read capacity).

#define B_ 8
#define S_ 4096
#define D_ 1024
#define SD4_ ((S_ * D_) / 4)   // 1,048,576 float4 tiles per batch slice

__global__ __launch_bounds__(256) void pe_add_kernel(
    const float4* __restrict__ x, float4* __restrict__ out)
{
    const int idx4 = blockIdx.x * blockDim.x + threadIdx.x;   // [0, SD4_)
    const int d0   = (idx4 & (D_ / 4 - 1)) << 2;              // element column in D
    const float sf = (float)(idx4 >> 8);                      // s = idx4 / 256

    // Front-batch all 8 batch-slice loads -> 8 outstanding LDG.128 per thread.
    float4 v[B_];
#pragma unroll
    for (int b = 0; b < B_; b++)
        v[b] = x[(long long)b * SD4_ + idx4];

    // Encoding float4, computed once, hidden under the in-flight loads.
    // angle(d) = s * 10000^(-d/D) = s * exp2(-d * log2(1e4)/D)
    const float c = -(13.287712379549449f / 1024.0f);
    const float e0 = sinf(sf * exp2f((float)(d0 + 0) * c));   // even d -> sin
    const float e1 = cosf(sf * exp2f((float)(d0 + 1) * c));   // odd d  -> cos
    const float e2 = sinf(sf * exp2f((float)(d0 + 2) * c));
    const float e3 = cosf(sf * exp2f((float)(d0 + 3) * c));

#pragma unroll
    for (int b = 0; b < B_; b++) {
        float4 r = v[b];
        r.x += e0; r.y += e1; r.z += e2; r.w += e3;
        __stcs(out + (long long)b * SD4_ + idx4, r);
    }
}

extern "C" void kernel_launch(void* const* d_in, const int* in_sizes, int n_in,
                              void* d_out, int out_size)
{
    const float4* x = (const float4*)d_in[0];
    float4* out = (float4*)d_out;
    pe_add_kernel<<<SD4_ / 256, 256>>>(x, out);
}